// round 12
// baseline (speedup 1.0000x reference)
#include <cuda_runtime.h>
#include <cuda_fp16.h>
#include <cstdint>
#include <math.h>

// Problem constants
constexpr int NNODES = 40000;
constexpr int NEDGES = 640000;
constexpr int D = 128;
constexpr int DH = 64;
constexpr int NCLS = 10;

constexpr int SCAN_BLK = 512;
constexpr int NPART = (NNODES + SCAN_BLK - 1) / SCAN_BLK;   // 79

// warp-level tensor core ops (arch-agnostic PTX: works on plain sm_100)
#define LDSM_X4(r0, r1, r2, r3, addr)                                          \
    asm volatile("ldmatrix.sync.aligned.m8n8.x4.shared.b16 {%0,%1,%2,%3}, [%4];" \
                 : "=r"(r0), "=r"(r1), "=r"(r2), "=r"(r3) : "r"(addr))

#define MMA16816(c, a, b)                                                       \
    asm volatile("mma.sync.aligned.m16n8k16.row.col.f32.f16.f16.f32 "           \
                 "{%0,%1,%2,%3}, {%4,%5,%6,%7}, {%8,%9}, {%0,%1,%2,%3};"        \
                 : "+f"((c)[0]), "+f"((c)[1]), "+f"((c)[2]), "+f"((c)[3])       \
                 : "r"((a)[0]), "r"((a)[1]), "r"((a)[2]), "r"((a)[3]),          \
                   "r"((b)[0]), "r"((b)[1]))

// single extern shared symbol (one type for the whole TU)
extern __shared__ char smem_raw[];

// ---------------------------------------------------------------------------
// Scratch. Feature buffer has a phantom zero row at index NNODES (static
// zero-init, never written) used to pad edge groups in the aggregation.
// ---------------------------------------------------------------------------
__device__ int    g_cnt_in[NNODES];
__device__ int    g_cnt_out[NNODES];
__device__ float  g_norm_in[NNODES];
__device__ float  g_norm_out[NNODES];
__device__ int    g_row_ptr[NNODES + 1];
__device__ int    g_cursor[NNODES];
__device__ int    g_esrc[NEDGES];                        // src per edge, CSR by dst
__device__ __half g_hf16[(size_t)(NNODES + 1) * D];      // pre-scaled features (+zero row)
__device__ __half g_agg [(size_t)NNODES * D];            // fp16 aggregation output
// one-time fp16 transposed weights (n-major [N][128])
__device__ __half g_w0t [D * D];     // [n][k]
__device__ __half g_w1t [D * D];
__device__ __half g_wl1t[DH * D];

__device__ __forceinline__ uint32_t smem_u32(const void* p) {
    uint32_t a;
    asm("{ .reg .u64 t; cvta.to.shared.u64 t, %1; cvt.u32.u64 %0, t; }" : "=r"(a) : "l"(p));
    return a;
}
__device__ __forceinline__ __half2 h2of(const uint4& q, int r) {
    return *reinterpret_cast<const __half2*>(&(&q.x)[r]);
}

// ---------------------------------------------------------------------------
// 0. one-time weight transpose+convert: W (k-major fp32) -> Wt (n-major fp16)
//    idx<2048: W0; idx<4096: W1; idx<5120: Wl1.  20 blocks x 256.
// ---------------------------------------------------------------------------
__global__ void wprep_kernel(const float* __restrict__ W0,
                             const float* __restrict__ W1,
                             const float* __restrict__ Wl1) {
    int idx = blockIdx.x * blockDim.x + threadIdx.x;
    __half hv[8];
    if (idx < 2048) {
        int n = idx >> 4, k0 = (idx & 15) << 3;
        #pragma unroll
        for (int j = 0; j < 8; j++) hv[j] = __float2half(__ldg(&W0[(k0 + j) * D + n]));
        *reinterpret_cast<uint4*>(&g_w0t[n * D + k0]) = *reinterpret_cast<uint4*>(hv);
    } else if (idx < 4096) {
        int t = idx - 2048;
        int n = t >> 4, k0 = (t & 15) << 3;
        #pragma unroll
        for (int j = 0; j < 8; j++) hv[j] = __float2half(__ldg(&W1[(k0 + j) * D + n]));
        *reinterpret_cast<uint4*>(&g_w1t[n * D + k0]) = *reinterpret_cast<uint4*>(hv);
    } else if (idx < 5120) {
        int t = idx - 4096;
        int n = t >> 4, k0 = (t & 15) << 3;
        #pragma unroll
        for (int j = 0; j < 8; j++) hv[j] = __float2half(__ldg(&Wl1[(k0 + j) * DH + n]));
        *reinterpret_cast<uint4*>(&g_wl1t[n * D + k0]) = *reinterpret_cast<uint4*>(hv);
    }
}

// ---------------------------------------------------------------------------
// 1. pure degree histogram
// ---------------------------------------------------------------------------
__global__ void hist_kernel(const int* __restrict__ src, const int* __restrict__ dst) {
    int e = blockIdx.x * blockDim.x + threadIdx.x;
    if (e < NEDGES) {
        atomicAdd(&g_cnt_out[src[e]], 1);
        atomicAdd(&g_cnt_in [dst[e]], 1);
    }
}

// ---------------------------------------------------------------------------
// 2. one-kernel scan + norms
// ---------------------------------------------------------------------------
__global__ void scan_norms_kernel() {
    const int base = blockIdx.x * SCAN_BLK;
    const int i    = base + threadIdx.x;
    const int tid  = threadIdx.x, lane = tid & 31, wid = tid >> 5;
    __shared__ int ws[SCAN_BLK / 32];
    __shared__ int s_off;

    int pv = 0;
    for (int j = tid; j < base; j += SCAN_BLK) pv += g_cnt_in[j];
    #pragma unroll
    for (int d = 16; d > 0; d >>= 1) pv += __shfl_xor_sync(0xffffffffu, pv, d);
    if (lane == 0) ws[wid] = pv;
    __syncthreads();
    if (tid == 0) {
        int o = 0;
        #pragma unroll
        for (int w = 0; w < SCAN_BLK / 32; w++) o += ws[w];
        s_off = o;
    }
    __syncthreads();

    int ci = 0;
    if (i < NNODES) {
        ci = g_cnt_in[i];
        int co = g_cnt_out[i];
        g_norm_in [i] = rsqrtf(fmaxf((float)ci, 1.0f));
        g_norm_out[i] = rsqrtf(fmaxf((float)co, 1.0f));
    }
    int incl = ci;
    #pragma unroll
    for (int d = 1; d < 32; d <<= 1) {
        int t = __shfl_up_sync(0xffffffffu, incl, d);
        if (lane >= d) incl += t;
    }
    if (lane == 31) ws[wid] = incl;
    __syncthreads();
    int woff = 0;
    for (int w = 0; w < wid; w++) woff += ws[w];
    int excl = incl - ci + woff + s_off;
    if (i < NNODES) { g_row_ptr[i] = excl; g_cursor[i] = excl; }
    if (i == 0) g_row_ptr[NNODES] = NEDGES;
}

// ---------------------------------------------------------------------------
// 3. scatter edges into CSR + pre-scaled fp16 input conversion; re-zero cnts
// ---------------------------------------------------------------------------
__global__ void scatter_conv_kernel(const int* __restrict__ src,
                                    const int* __restrict__ dst,
                                    const float* __restrict__ h) {
    int e = blockIdx.x * blockDim.x + threadIdx.x;
    if (e < NEDGES) {
        int pos = atomicAdd(&g_cursor[dst[e]], 1);
        g_esrc[pos] = src[e];

        // feat[node] = norm_out[node] * h[node]   (node = e/16)
        const float w = __ldg(&g_norm_out[e >> 4]);
        const float4* s4 = reinterpret_cast<const float4*>(h);
        float4 a = __ldg(&s4[e * 2]);
        float4 b = __ldg(&s4[e * 2 + 1]);
        __half2 p0 = __floats2half2_rn(a.x * w, a.y * w);
        __half2 p1 = __floats2half2_rn(a.z * w, a.w * w);
        __half2 p2 = __floats2half2_rn(b.x * w, b.y * w);
        __half2 p3 = __floats2half2_rn(b.z * w, b.w * w);
        uint4 o;
        o.x = *reinterpret_cast<unsigned*>(&p0);
        o.y = *reinterpret_cast<unsigned*>(&p1);
        o.z = *reinterpret_cast<unsigned*>(&p2);
        o.w = *reinterpret_cast<unsigned*>(&p3);
        reinterpret_cast<uint4*>(g_hf16)[e] = o;
    }
    if (e < NNODES) { g_cnt_in[e] = 0; g_cnt_out[e] = 0; }
}

// ---------------------------------------------------------------------------
// 4. aggregation: half-warp per node; pre-scaled features -> pure gather-sum.
//    Flat 4-edge groups (phantom zero row pads), depth-2 fp16 tree, fp32 flush.
//    launch_bounds(256,6) keeps regs <=42 for high occupancy (latency-bound).
// ---------------------------------------------------------------------------
__global__ void __launch_bounds__(256, 6)
aggregate_kernel(const __half* __restrict__ hin, __half* __restrict__ aggout) {
    const int gw = (blockIdx.x * blockDim.x + threadIdx.x) >> 4;   // node
    const int sl = threadIdx.x & 15;                               // sublane
    if (gw >= NNODES) return;
    const unsigned hm = (threadIdx.x & 16) ? 0xFFFF0000u : 0x0000FFFFu;
    const int beg = g_row_ptr[gw];
    const int end = g_row_ptr[gw + 1];

    float acc[8] = {0.f, 0.f, 0.f, 0.f, 0.f, 0.f, 0.f, 0.f};
    const uint4* feat = reinterpret_cast<const uint4*>(hin);

    for (int base = beg; base < end; base += 16) {
        // lanes with edge index >= end point at the phantom zero row
        int my = (base + sl < end) ? __ldg(&g_esrc[base + sl]) : NNODES;
        const int n = min(end - base, 16);
        for (int j = 0; j < n; j += 4) {
            uint4 q[4];
            #pragma unroll
            for (int k = 0; k < 4; k++) {
                int s = __shfl_sync(hm, my, j + k, 16);
                q[k] = __ldg(feat + (size_t)s * 16 + sl);
            }
            #pragma unroll
            for (int rr = 0; rr < 4; rr++) {
                __half2 t01 = __hadd2(h2of(q[0], rr), h2of(q[1], rr));
                __half2 t23 = __hadd2(h2of(q[2], rr), h2of(q[3], rr));
                float2 f = __half22float2(__hadd2(t01, t23));
                acc[2 * rr]     += f.x;
                acc[2 * rr + 1] += f.y;
            }
        }
    }

    const float win = g_norm_in[gw];
    __half2 p0 = __floats2half2_rn(acc[0] * win, acc[1] * win);
    __half2 p1 = __floats2half2_rn(acc[2] * win, acc[3] * win);
    __half2 p2 = __floats2half2_rn(acc[4] * win, acc[5] * win);
    __half2 p3 = __floats2half2_rn(acc[6] * win, acc[7] * win);
    uint4 o;
    o.x = *reinterpret_cast<unsigned*>(&p0);
    o.y = *reinterpret_cast<unsigned*>(&p1);
    o.z = *reinterpret_cast<unsigned*>(&p2);
    o.w = *reinterpret_cast<unsigned*>(&p3);
    reinterpret_cast<uint4*>(aggout)[(size_t)gw * 16 + sl] = o;
}

// ---------------------------------------------------------------------------
// 5. HMMA GEMM + bias + relu (+ optional norm_out pre-scale of output):
//    out = relu(agg @ W + b) * (SCALE_OUT ? norm_out : 1),  fp16 out.
//    B staged from the pre-transposed fp16 weights (coalesced).
// ---------------------------------------------------------------------------
constexpr int MMS = 136;                           // smem row stride in halves
constexpr int MM_SMEM_BYTES = 2 * 128 * MMS * 2;   // As + Bs = 69632 B

template <bool SCALE_OUT>
__global__ void __launch_bounds__(256)
mma_gemm_kernel(const __half* __restrict__ A,     // [NNODES][128] fp16
                const __half* __restrict__ Wt,    // [128][128] fp16 n-major
                const float* __restrict__ bias,   // [128]
                __half* __restrict__ outp) {      // [(NNODES+1)][128] fp16
    __half* As = reinterpret_cast<__half*>(smem_raw);      // [128][MMS]
    __half* Bs = As + 128 * MMS;                           // [128][MMS] (Bs[n][k]=W[k][n])

    const int tid  = threadIdx.x;
    const int wid  = tid >> 5;
    const int lane = tid & 31;
    const int row0 = blockIdx.x * 128;

    for (int idx = tid; idx < 2048; idx += 256) {
        int r  = idx >> 4;
        int c8 = (idx & 15) << 3;
        uint4 v = make_uint4(0u, 0u, 0u, 0u);
        if (row0 + r < NNODES)
            v = *reinterpret_cast<const uint4*>(A + (size_t)(row0 + r) * D + c8);
        *reinterpret_cast<uint4*>(&As[r * MMS + c8]) = v;
    }
    for (int idx = tid; idx < 2048; idx += 256) {
        int n  = idx >> 4;
        int k0 = (idx & 15) << 3;
        *reinterpret_cast<uint4*>(&Bs[n * MMS + k0]) =
            *reinterpret_cast<const uint4*>(Wt + n * D + k0);
    }
    __syncthreads();

    const int warpM = wid & 3;
    const int warpN = wid >> 2;

    const uint32_t sbA = smem_u32(As);
    const uint32_t sbB = smem_u32(Bs);
    const int arow = warpM * 32 + (((lane >> 3) & 1) << 3) + (lane & 7);
    const int acol = (lane >> 4) << 3;
    uint32_t aaddr = sbA + (uint32_t)(arow * MMS + acol) * 2;
    const int brow = warpN * 64 + ((lane >> 4) << 3) + (lane & 7);
    const int bcol = lane & 8;
    uint32_t baddr = sbB + (uint32_t)(brow * MMS + bcol) * 2;

    float acc[2][8][4];
    #pragma unroll
    for (int mi = 0; mi < 2; mi++)
        #pragma unroll
        for (int ni = 0; ni < 8; ni++)
            #pragma unroll
            for (int q = 0; q < 4; q++) acc[mi][ni][q] = 0.f;

    #pragma unroll
    for (int ks = 0; ks < 8; ks++) {
        const uint32_t koff = (uint32_t)ks * 32;
        uint32_t a[2][4];
        LDSM_X4(a[0][0], a[0][1], a[0][2], a[0][3], aaddr + koff);
        LDSM_X4(a[1][0], a[1][1], a[1][2], a[1][3], aaddr + koff + (uint32_t)(16 * MMS * 2));
        uint32_t b[8][2];
        #pragma unroll
        for (int g = 0; g < 4; g++) {
            LDSM_X4(b[g * 2][0], b[g * 2][1], b[g * 2 + 1][0], b[g * 2 + 1][1],
                    baddr + koff + (uint32_t)(g * 16 * MMS * 2));
        }
        #pragma unroll
        for (int mi = 0; mi < 2; mi++)
            #pragma unroll
            for (int ni = 0; ni < 8; ni++)
                MMA16816(acc[mi][ni], a[mi], b[ni]);
    }

    const int gid = lane >> 2;
    const int tig = lane & 3;
    #pragma unroll
    for (int mi = 0; mi < 2; mi++) {
        const int r_lo = row0 + warpM * 32 + mi * 16 + gid;
        #pragma unroll
        for (int half = 0; half < 2; half++) {
            const int orow = r_lo + half * 8;
            if (orow >= NNODES) continue;
            float sc = 1.0f;
            if (SCALE_OUT) sc = __ldg(&g_norm_out[orow]);
            #pragma unroll
            for (int ni = 0; ni < 8; ni++) {
                const int col = warpN * 64 + ni * 8 + tig * 2;
                float v0 = fmaxf(acc[mi][ni][half * 2 + 0] + __ldg(&bias[col]), 0.f);
                float v1 = fmaxf(acc[mi][ni][half * 2 + 1] + __ldg(&bias[col + 1]), 0.f);
                if (SCALE_OUT) { v0 *= sc; v1 *= sc; }
                __half2 q = __floats2half2_rn(v0, v1);
                *reinterpret_cast<__half2*>(outp + (size_t)orow * D + col) = q;
            }
        }
    }
}

// ---------------------------------------------------------------------------
// 6. fused HMMA MLP head: t = relu(h2 @ Wl1 + bl1) [64], out = t @ Wl2 + bl2
// ---------------------------------------------------------------------------
constexpr int HD_SMEM_BYTES = 2 * 64 * MMS * 2;   // As + Bs = 34816 B

__global__ void __launch_bounds__(128)
head_kernel(const __half* __restrict__ A,      // h2 [(NNODES+1)][128] fp16
            const __half* __restrict__ Wl1t,   // [64][128] fp16 n-major
            const float* __restrict__ bl1,     // [64]
            const float* __restrict__ Wl2,     // [64][10]
            const float* __restrict__ bl2,     // [10]
            float* __restrict__ out) {         // [NNODES][10]
    __half* As = reinterpret_cast<__half*>(smem_raw);   // [64][MMS]
    __half* Bs = As + 64 * MMS;                         // [64][MMS]
    float* Ts  = reinterpret_cast<float*>(smem_raw);    // [64][65] (phase 2)
    float* W2s = Ts + 64 * 65;
    float* b2s = W2s + DH * NCLS;

    const int tid  = threadIdx.x;
    const int wid  = tid >> 5;
    const int lane = tid & 31;
    const int row0 = blockIdx.x * 64;

    for (int idx = tid; idx < 1024; idx += 128) {
        int r  = idx >> 4;
        int c8 = (idx & 15) << 3;
        *reinterpret_cast<uint4*>(&As[r * MMS + c8]) =
            *reinterpret_cast<const uint4*>(A + (size_t)(row0 + r) * D + c8);
    }
    for (int idx = tid; idx < 1024; idx += 128) {
        int n  = idx >> 4;
        int k0 = (idx & 15) << 3;
        *reinterpret_cast<uint4*>(&Bs[n * MMS + k0]) =
            *reinterpret_cast<const uint4*>(Wl1t + n * D + k0);
    }
    __syncthreads();

    const uint32_t sbA = smem_u32(As);
    const uint32_t sbB = smem_u32(Bs);
    const int arow = wid * 16 + (((lane >> 3) & 1) << 3) + (lane & 7);
    const int acol = (lane >> 4) << 3;
    uint32_t aaddr = sbA + (uint32_t)(arow * MMS + acol) * 2;
    const int brow = ((lane >> 4) << 3) + (lane & 7);
    const int bcol = lane & 8;
    uint32_t baddr = sbB + (uint32_t)(brow * MMS + bcol) * 2;

    float acc[8][4];
    #pragma unroll
    for (int ni = 0; ni < 8; ni++)
        #pragma unroll
        for (int q = 0; q < 4; q++) acc[ni][q] = 0.f;

    #pragma unroll
    for (int ks = 0; ks < 8; ks++) {
        const uint32_t koff = (uint32_t)ks * 32;
        uint32_t a[4];
        LDSM_X4(a[0], a[1], a[2], a[3], aaddr + koff);
        uint32_t b[8][2];
        #pragma unroll
        for (int g = 0; g < 4; g++) {
            LDSM_X4(b[g * 2][0], b[g * 2][1], b[g * 2 + 1][0], b[g * 2 + 1][1],
                    baddr + koff + (uint32_t)(g * 16 * MMS * 2));
        }
        #pragma unroll
        for (int ni = 0; ni < 8; ni++)
            MMA16816(acc[ni], a, b[ni]);
    }

    __syncthreads();

    const int gid = lane >> 2;
    const int tig = lane & 3;
    #pragma unroll
    for (int half = 0; half < 2; half++) {
        const int r = wid * 16 + half * 8 + gid;
        #pragma unroll
        for (int ni = 0; ni < 8; ni++) {
            const int col = ni * 8 + tig * 2;
            Ts[r * 65 + col]     = fmaxf(acc[ni][half * 2 + 0] + __ldg(&bl1[col]), 0.f);
            Ts[r * 65 + col + 1] = fmaxf(acc[ni][half * 2 + 1] + __ldg(&bl1[col + 1]), 0.f);
        }
    }
    for (int i = tid; i < DH * NCLS; i += 128) W2s[i] = Wl2[i];
    if (tid < NCLS) b2s[tid] = bl2[tid];
    __syncthreads();

    if (tid < 64) {
        float s[NCLS];
        #pragma unroll
        for (int c = 0; c < NCLS; c++) s[c] = b2s[c];
        #pragma unroll 4
        for (int k = 0; k < DH; k++) {
            float a = Ts[tid * 65 + k];
            #pragma unroll
            for (int c = 0; c < NCLS; c++) s[c] = fmaf(a, W2s[k * NCLS + c], s[c]);
        }
        float* o = out + (size_t)(row0 + tid) * NCLS;
        #pragma unroll
        for (int c = 0; c < NCLS; c++) o[c] = s[c];
    }
}

// ---------------------------------------------------------------------------
// launch
// ---------------------------------------------------------------------------
extern "C" void kernel_launch(void* const* d_in, const int* in_sizes, int n_in,
                              void* d_out, int out_size) {
    const float* h   = (const float*)d_in[0];
    const int*   src = (const int*)  d_in[1];
    const int*   dst = (const int*)  d_in[2];
    const float* W0  = (const float*)d_in[3];
    const float* b0  = (const float*)d_in[4];
    const float* W1  = (const float*)d_in[5];
    const float* b1  = (const float*)d_in[6];
    const float* Wl1 = (const float*)d_in[7];
    const float* bl1 = (const float*)d_in[8];
    const float* Wl2 = (const float*)d_in[9];
    const float* bl2 = (const float*)d_in[10];
    float* out = (float*)d_out;

    void *p_agg, *p_hf, *p_w0t, *p_w1t, *p_wl1t;
    cudaGetSymbolAddress(&p_agg,  g_agg);
    cudaGetSymbolAddress(&p_hf,   g_hf16);
    cudaGetSymbolAddress(&p_w0t,  g_w0t);
    cudaGetSymbolAddress(&p_w1t,  g_w1t);
    cudaGetSymbolAddress(&p_wl1t, g_wl1t);
    __half* agg  = (__half*)p_agg;
    __half* hf   = (__half*)p_hf;
    __half* w0t  = (__half*)p_w0t;
    __half* w1t  = (__half*)p_w1t;
    __half* wl1t = (__half*)p_wl1t;

    cudaFuncSetAttribute(mma_gemm_kernel<true>,
                         cudaFuncAttributeMaxDynamicSharedMemorySize, MM_SMEM_BYTES);
    cudaFuncSetAttribute(mma_gemm_kernel<false>,
                         cudaFuncAttributeMaxDynamicSharedMemorySize, MM_SMEM_BYTES);
    cudaFuncSetAttribute(head_kernel,
                         cudaFuncAttributeMaxDynamicSharedMemorySize, HD_SMEM_BYTES);

    const int NB_E = (NEDGES + 255) / 256;
    const int NB_A = (NNODES * 16 + 255) / 256;       // half-warp-per-node grid
    const int NB_M = (NNODES + 127) / 128;            // 313 MMA tiles
    const int NB_H = NNODES / 64;                     // 625 head tiles

    // preprocessing: 4 launches (wprep is tiny and independent)
    wprep_kernel<<<20, 256>>>(W0, W1, Wl1);
    hist_kernel<<<NB_E, 256>>>(src, dst);
    scan_norms_kernel<<<NPART, SCAN_BLK>>>();
    scatter_conv_kernel<<<NB_E, 256>>>(src, dst, h);

    // layer 0 (GEMM writes h1 pre-scaled by norm_out for the next aggregation)
    aggregate_kernel<<<NB_A, 256>>>(hf, agg);
    mma_gemm_kernel<true><<<NB_M, 256, MM_SMEM_BYTES>>>(agg, w0t, b0, hf);
    // layer 1 (plain output; feeds the head)
    aggregate_kernel<<<NB_A, 256>>>(hf, agg);
    mma_gemm_kernel<false><<<NB_M, 256, MM_SMEM_BYTES>>>(agg, w1t, b1, hf);
    // fused HMMA MLP head
    head_kernel<<<NB_H, 128, HD_SMEM_BYTES>>>(hf, wl1t, bl1, Wl2, bl2, out);
}

// round 13
// speedup vs baseline: 1.0195x; 1.0195x over previous
#include <cuda_runtime.h>
#include <cuda_fp16.h>
#include <cstdint>
#include <math.h>

// Problem constants
constexpr int NNODES = 40000;
constexpr int NEDGES = 640000;
constexpr int D = 128;
constexpr int DH = 64;
constexpr int NCLS = 10;

constexpr int SCAN_BLK = 512;
constexpr int NPART = (NNODES + SCAN_BLK - 1) / SCAN_BLK;   // 79

// warp-level tensor core ops (arch-agnostic PTX: works on plain sm_100)
#define LDSM_X4(r0, r1, r2, r3, addr)                                          \
    asm volatile("ldmatrix.sync.aligned.m8n8.x4.shared.b16 {%0,%1,%2,%3}, [%4];" \
                 : "=r"(r0), "=r"(r1), "=r"(r2), "=r"(r3) : "r"(addr))

#define MMA16816(c, a, b)                                                       \
    asm volatile("mma.sync.aligned.m16n8k16.row.col.f32.f16.f16.f32 "           \
                 "{%0,%1,%2,%3}, {%4,%5,%6,%7}, {%8,%9}, {%0,%1,%2,%3};"        \
                 : "+f"((c)[0]), "+f"((c)[1]), "+f"((c)[2]), "+f"((c)[3])       \
                 : "r"((a)[0]), "r"((a)[1]), "r"((a)[2]), "r"((a)[3]),          \
                   "r"((b)[0]), "r"((b)[1]))

// single extern shared symbol (one type for the whole TU)
extern __shared__ char smem_raw[];

// ---------------------------------------------------------------------------
// Scratch. Feature buffer has a phantom zero row at index NNODES (static
// zero-init, never written) used to pad edge groups in the aggregation.
// ---------------------------------------------------------------------------
__device__ int    g_cnt_in[NNODES];
__device__ int    g_cnt_out[NNODES];
__device__ float  g_norm_in[NNODES];
__device__ float  g_norm_out[NNODES];
__device__ int    g_row_ptr[NNODES + 1];
__device__ int    g_cursor[NNODES];
__device__ int    g_esrc[NEDGES];                        // src per edge, CSR by dst
__device__ __half g_hf16[(size_t)(NNODES + 1) * D];      // pre-scaled features (+zero row)
__device__ __half g_agg [(size_t)NNODES * D];            // fp16 aggregation output
// one-time fp16 transposed weights (n-major [N][128])
__device__ __half g_w0t [D * D];     // [n][k]
__device__ __half g_w1t [D * D];
__device__ __half g_wl1t[DH * D];

__device__ __forceinline__ uint32_t smem_u32(const void* p) {
    uint32_t a;
    asm("{ .reg .u64 t; cvta.to.shared.u64 t, %1; cvt.u32.u64 %0, t; }" : "=r"(a) : "l"(p));
    return a;
}
__device__ __forceinline__ __half2 h2of(const uint4& q, int r) {
    return *reinterpret_cast<const __half2*>(&(&q.x)[r]);
}

// ---------------------------------------------------------------------------
// 1. degree histogram + (first 5120 threads) one-time weight transpose->fp16
// ---------------------------------------------------------------------------
__global__ void hist_wprep_kernel(const int* __restrict__ src,
                                  const int* __restrict__ dst,
                                  const float* __restrict__ W0,
                                  const float* __restrict__ W1,
                                  const float* __restrict__ Wl1) {
    int e = blockIdx.x * blockDim.x + threadIdx.x;
    if (e < NEDGES) {
        atomicAdd(&g_cnt_out[src[e]], 1);
        atomicAdd(&g_cnt_in [dst[e]], 1);
    }
    if (e < 5120) {
        __half hv[8];
        if (e < 2048) {
            int n = e >> 4, k0 = (e & 15) << 3;
            #pragma unroll
            for (int j = 0; j < 8; j++) hv[j] = __float2half(__ldg(&W0[(k0 + j) * D + n]));
            *reinterpret_cast<uint4*>(&g_w0t[n * D + k0]) = *reinterpret_cast<uint4*>(hv);
        } else if (e < 4096) {
            int t = e - 2048;
            int n = t >> 4, k0 = (t & 15) << 3;
            #pragma unroll
            for (int j = 0; j < 8; j++) hv[j] = __float2half(__ldg(&W1[(k0 + j) * D + n]));
            *reinterpret_cast<uint4*>(&g_w1t[n * D + k0]) = *reinterpret_cast<uint4*>(hv);
        } else {
            int t = e - 4096;
            int n = t >> 4, k0 = (t & 15) << 3;
            #pragma unroll
            for (int j = 0; j < 8; j++) hv[j] = __float2half(__ldg(&Wl1[(k0 + j) * DH + n]));
            *reinterpret_cast<uint4*>(&g_wl1t[n * D + k0]) = *reinterpret_cast<uint4*>(hv);
        }
    }
}

// ---------------------------------------------------------------------------
// 2. one-kernel scan + norms
// ---------------------------------------------------------------------------
__global__ void scan_norms_kernel() {
    const int base = blockIdx.x * SCAN_BLK;
    const int i    = base + threadIdx.x;
    const int tid  = threadIdx.x, lane = tid & 31, wid = tid >> 5;
    __shared__ int ws[SCAN_BLK / 32];
    __shared__ int s_off;

    int pv = 0;
    for (int j = tid; j < base; j += SCAN_BLK) pv += g_cnt_in[j];
    #pragma unroll
    for (int d = 16; d > 0; d >>= 1) pv += __shfl_xor_sync(0xffffffffu, pv, d);
    if (lane == 0) ws[wid] = pv;
    __syncthreads();
    if (tid == 0) {
        int o = 0;
        #pragma unroll
        for (int w = 0; w < SCAN_BLK / 32; w++) o += ws[w];
        s_off = o;
    }
    __syncthreads();

    int ci = 0;
    if (i < NNODES) {
        ci = g_cnt_in[i];
        int co = g_cnt_out[i];
        g_norm_in [i] = rsqrtf(fmaxf((float)ci, 1.0f));
        g_norm_out[i] = rsqrtf(fmaxf((float)co, 1.0f));
    }
    int incl = ci;
    #pragma unroll
    for (int d = 1; d < 32; d <<= 1) {
        int t = __shfl_up_sync(0xffffffffu, incl, d);
        if (lane >= d) incl += t;
    }
    if (lane == 31) ws[wid] = incl;
    __syncthreads();
    int woff = 0;
    for (int w = 0; w < wid; w++) woff += ws[w];
    int excl = incl - ci + woff + s_off;
    if (i < NNODES) { g_row_ptr[i] = excl; g_cursor[i] = excl; }
    if (i == 0) g_row_ptr[NNODES] = NEDGES;
}

// ---------------------------------------------------------------------------
// 3. scatter edges into CSR + pre-scaled fp16 input conversion; re-zero cnts
// ---------------------------------------------------------------------------
__global__ void scatter_conv_kernel(const int* __restrict__ src,
                                    const int* __restrict__ dst,
                                    const float* __restrict__ h) {
    int e = blockIdx.x * blockDim.x + threadIdx.x;
    if (e < NEDGES) {
        int pos = atomicAdd(&g_cursor[dst[e]], 1);
        g_esrc[pos] = src[e];

        // feat[node] = norm_out[node] * h[node]   (node = e/16)
        const float w = __ldg(&g_norm_out[e >> 4]);
        const float4* s4 = reinterpret_cast<const float4*>(h);
        float4 a = __ldg(&s4[e * 2]);
        float4 b = __ldg(&s4[e * 2 + 1]);
        __half2 p0 = __floats2half2_rn(a.x * w, a.y * w);
        __half2 p1 = __floats2half2_rn(a.z * w, a.w * w);
        __half2 p2 = __floats2half2_rn(b.x * w, b.y * w);
        __half2 p3 = __floats2half2_rn(b.z * w, b.w * w);
        uint4 o;
        o.x = *reinterpret_cast<unsigned*>(&p0);
        o.y = *reinterpret_cast<unsigned*>(&p1);
        o.z = *reinterpret_cast<unsigned*>(&p2);
        o.w = *reinterpret_cast<unsigned*>(&p3);
        reinterpret_cast<uint4*>(g_hf16)[e] = o;
    }
    if (e < NNODES) { g_cnt_in[e] = 0; g_cnt_out[e] = 0; }
}

// ---------------------------------------------------------------------------
// 4. aggregation: half-warp per node; pre-scaled features -> pure gather-sum.
//    Flat 8-edge groups (phantom zero row pads), depth-3 fp16 tree, fp32 flush.
//    (round-11 best-measured variant: no launch_bounds cap, 8-wide MLP)
// ---------------------------------------------------------------------------
__global__ void aggregate_kernel(const __half* __restrict__ hin, __half* __restrict__ aggout) {
    const int gw = (blockIdx.x * blockDim.x + threadIdx.x) >> 4;   // node
    const int sl = threadIdx.x & 15;                               // sublane
    if (gw >= NNODES) return;
    const unsigned hm = (threadIdx.x & 16) ? 0xFFFF0000u : 0x0000FFFFu;
    const int beg = g_row_ptr[gw];
    const int end = g_row_ptr[gw + 1];

    float acc[8] = {0.f, 0.f, 0.f, 0.f, 0.f, 0.f, 0.f, 0.f};
    const uint4* feat = reinterpret_cast<const uint4*>(hin);

    for (int base = beg; base < end; base += 16) {
        // lanes with edge index >= end point at the phantom zero row
        int my = (base + sl < end) ? __ldg(&g_esrc[base + sl]) : NNODES;
        const int n = min(end - base, 16);
        for (int j = 0; j < n; j += 8) {
            uint4 q[8];
            #pragma unroll
            for (int k = 0; k < 8; k++) {
                int s = __shfl_sync(hm, my, j + k, 16);
                q[k] = __ldg(feat + (size_t)s * 16 + sl);
            }
            #pragma unroll
            for (int rr = 0; rr < 4; rr++) {
                __half2 t01 = __hadd2(h2of(q[0], rr), h2of(q[1], rr));
                __half2 t23 = __hadd2(h2of(q[2], rr), h2of(q[3], rr));
                __half2 t45 = __hadd2(h2of(q[4], rr), h2of(q[5], rr));
                __half2 t67 = __hadd2(h2of(q[6], rr), h2of(q[7], rr));
                float2 f = __half22float2(__hadd2(__hadd2(t01, t23), __hadd2(t45, t67)));
                acc[2 * rr]     += f.x;
                acc[2 * rr + 1] += f.y;
            }
        }
    }

    const float win = g_norm_in[gw];
    __half2 p0 = __floats2half2_rn(acc[0] * win, acc[1] * win);
    __half2 p1 = __floats2half2_rn(acc[2] * win, acc[3] * win);
    __half2 p2 = __floats2half2_rn(acc[4] * win, acc[5] * win);
    __half2 p3 = __floats2half2_rn(acc[6] * win, acc[7] * win);
    uint4 o;
    o.x = *reinterpret_cast<unsigned*>(&p0);
    o.y = *reinterpret_cast<unsigned*>(&p1);
    o.z = *reinterpret_cast<unsigned*>(&p2);
    o.w = *reinterpret_cast<unsigned*>(&p3);
    reinterpret_cast<uint4*>(aggout)[(size_t)gw * 16 + sl] = o;
}

// ---------------------------------------------------------------------------
// 5. HMMA GEMM + bias + relu (+ optional norm_out pre-scale of output):
//    out = relu(agg @ W + b) * (SCALE_OUT ? norm_out : 1),  fp16 out.
//    B staged from the pre-transposed fp16 weights (coalesced).
// ---------------------------------------------------------------------------
constexpr int MMS = 136;                           // smem row stride in halves
constexpr int MM_SMEM_BYTES = 2 * 128 * MMS * 2;   // As + Bs = 69632 B

template <bool SCALE_OUT>
__global__ void __launch_bounds__(256)
mma_gemm_kernel(const __half* __restrict__ A,     // [NNODES][128] fp16
                const __half* __restrict__ Wt,    // [128][128] fp16 n-major
                const float* __restrict__ bias,   // [128]
                __half* __restrict__ outp) {      // [(NNODES+1)][128] fp16
    __half* As = reinterpret_cast<__half*>(smem_raw);      // [128][MMS]
    __half* Bs = As + 128 * MMS;                           // [128][MMS] (Bs[n][k]=W[k][n])

    const int tid  = threadIdx.x;
    const int wid  = tid >> 5;
    const int lane = tid & 31;
    const int row0 = blockIdx.x * 128;

    for (int idx = tid; idx < 2048; idx += 256) {
        int r  = idx >> 4;
        int c8 = (idx & 15) << 3;
        uint4 v = make_uint4(0u, 0u, 0u, 0u);
        if (row0 + r < NNODES)
            v = *reinterpret_cast<const uint4*>(A + (size_t)(row0 + r) * D + c8);
        *reinterpret_cast<uint4*>(&As[r * MMS + c8]) = v;
    }
    for (int idx = tid; idx < 2048; idx += 256) {
        int n  = idx >> 4;
        int k0 = (idx & 15) << 3;
        *reinterpret_cast<uint4*>(&Bs[n * MMS + k0]) =
            *reinterpret_cast<const uint4*>(Wt + n * D + k0);
    }
    __syncthreads();

    const int warpM = wid & 3;
    const int warpN = wid >> 2;

    const uint32_t sbA = smem_u32(As);
    const uint32_t sbB = smem_u32(Bs);
    const int arow = warpM * 32 + (((lane >> 3) & 1) << 3) + (lane & 7);
    const int acol = (lane >> 4) << 3;
    uint32_t aaddr = sbA + (uint32_t)(arow * MMS + acol) * 2;
    const int brow = warpN * 64 + ((lane >> 4) << 3) + (lane & 7);
    const int bcol = lane & 8;
    uint32_t baddr = sbB + (uint32_t)(brow * MMS + bcol) * 2;

    float acc[2][8][4];
    #pragma unroll
    for (int mi = 0; mi < 2; mi++)
        #pragma unroll
        for (int ni = 0; ni < 8; ni++)
            #pragma unroll
            for (int q = 0; q < 4; q++) acc[mi][ni][q] = 0.f;

    #pragma unroll
    for (int ks = 0; ks < 8; ks++) {
        const uint32_t koff = (uint32_t)ks * 32;
        uint32_t a[2][4];
        LDSM_X4(a[0][0], a[0][1], a[0][2], a[0][3], aaddr + koff);
        LDSM_X4(a[1][0], a[1][1], a[1][2], a[1][3], aaddr + koff + (uint32_t)(16 * MMS * 2));
        uint32_t b[8][2];
        #pragma unroll
        for (int g = 0; g < 4; g++) {
            LDSM_X4(b[g * 2][0], b[g * 2][1], b[g * 2 + 1][0], b[g * 2 + 1][1],
                    baddr + koff + (uint32_t)(g * 16 * MMS * 2));
        }
        #pragma unroll
        for (int mi = 0; mi < 2; mi++)
            #pragma unroll
            for (int ni = 0; ni < 8; ni++)
                MMA16816(acc[mi][ni], a[mi], b[ni]);
    }

    const int gid = lane >> 2;
    const int tig = lane & 3;
    #pragma unroll
    for (int mi = 0; mi < 2; mi++) {
        const int r_lo = row0 + warpM * 32 + mi * 16 + gid;
        #pragma unroll
        for (int half = 0; half < 2; half++) {
            const int orow = r_lo + half * 8;
            if (orow >= NNODES) continue;
            float sc = 1.0f;
            if (SCALE_OUT) sc = __ldg(&g_norm_out[orow]);
            #pragma unroll
            for (int ni = 0; ni < 8; ni++) {
                const int col = warpN * 64 + ni * 8 + tig * 2;
                float v0 = fmaxf(acc[mi][ni][half * 2 + 0] + __ldg(&bias[col]), 0.f);
                float v1 = fmaxf(acc[mi][ni][half * 2 + 1] + __ldg(&bias[col + 1]), 0.f);
                if (SCALE_OUT) { v0 *= sc; v1 *= sc; }
                __half2 q = __floats2half2_rn(v0, v1);
                *reinterpret_cast<__half2*>(outp + (size_t)orow * D + col) = q;
            }
        }
    }
}

// ---------------------------------------------------------------------------
// 6. fused HMMA MLP head: t = relu(h2 @ Wl1 + bl1) [64], out = t @ Wl2 + bl2
// ---------------------------------------------------------------------------
constexpr int HD_SMEM_BYTES = 2 * 64 * MMS * 2;   // As + Bs = 34816 B

__global__ void __launch_bounds__(128)
head_kernel(const __half* __restrict__ A,      // h2 [(NNODES+1)][128] fp16
            const __half* __restrict__ Wl1t,   // [64][128] fp16 n-major
            const float* __restrict__ bl1,     // [64]
            const float* __restrict__ Wl2,     // [64][10]
            const float* __restrict__ bl2,     // [10]
            float* __restrict__ out) {         // [NNODES][10]
    __half* As = reinterpret_cast<__half*>(smem_raw);   // [64][MMS]
    __half* Bs = As + 64 * MMS;                         // [64][MMS]
    float* Ts  = reinterpret_cast<float*>(smem_raw);    // [64][65] (phase 2)
    float* W2s = Ts + 64 * 65;
    float* b2s = W2s + DH * NCLS;

    const int tid  = threadIdx.x;
    const int wid  = tid >> 5;
    const int lane = tid & 31;
    const int row0 = blockIdx.x * 64;

    for (int idx = tid; idx < 1024; idx += 128) {
        int r  = idx >> 4;
        int c8 = (idx & 15) << 3;
        *reinterpret_cast<uint4*>(&As[r * MMS + c8]) =
            *reinterpret_cast<const uint4*>(A + (size_t)(row0 + r) * D + c8);
    }
    for (int idx = tid; idx < 1024; idx += 128) {
        int n  = idx >> 4;
        int k0 = (idx & 15) << 3;
        *reinterpret_cast<uint4*>(&Bs[n * MMS + k0]) =
            *reinterpret_cast<const uint4*>(Wl1t + n * D + k0);
    }
    __syncthreads();

    const uint32_t sbA = smem_u32(As);
    const uint32_t sbB = smem_u32(Bs);
    const int arow = wid * 16 + (((lane >> 3) & 1) << 3) + (lane & 7);
    const int acol = (lane >> 4) << 3;
    uint32_t aaddr = sbA + (uint32_t)(arow * MMS + acol) * 2;
    const int brow = ((lane >> 4) << 3) + (lane & 7);
    const int bcol = lane & 8;
    uint32_t baddr = sbB + (uint32_t)(brow * MMS + bcol) * 2;

    float acc[8][4];
    #pragma unroll
    for (int ni = 0; ni < 8; ni++)
        #pragma unroll
        for (int q = 0; q < 4; q++) acc[ni][q] = 0.f;

    #pragma unroll
    for (int ks = 0; ks < 8; ks++) {
        const uint32_t koff = (uint32_t)ks * 32;
        uint32_t a[4];
        LDSM_X4(a[0], a[1], a[2], a[3], aaddr + koff);
        uint32_t b[8][2];
        #pragma unroll
        for (int g = 0; g < 4; g++) {
            LDSM_X4(b[g * 2][0], b[g * 2][1], b[g * 2 + 1][0], b[g * 2 + 1][1],
                    baddr + koff + (uint32_t)(g * 16 * MMS * 2));
        }
        #pragma unroll
        for (int ni = 0; ni < 8; ni++)
            MMA16816(acc[ni], a, b[ni]);
    }

    __syncthreads();

    const int gid = lane >> 2;
    const int tig = lane & 3;
    #pragma unroll
    for (int half = 0; half < 2; half++) {
        const int r = wid * 16 + half * 8 + gid;
        #pragma unroll
        for (int ni = 0; ni < 8; ni++) {
            const int col = ni * 8 + tig * 2;
            Ts[r * 65 + col]     = fmaxf(acc[ni][half * 2 + 0] + __ldg(&bl1[col]), 0.f);
            Ts[r * 65 + col + 1] = fmaxf(acc[ni][half * 2 + 1] + __ldg(&bl1[col + 1]), 0.f);
        }
    }
    for (int i = tid; i < DH * NCLS; i += 128) W2s[i] = Wl2[i];
    if (tid < NCLS) b2s[tid] = bl2[tid];
    __syncthreads();

    if (tid < 64) {
        float s[NCLS];
        #pragma unroll
        for (int c = 0; c < NCLS; c++) s[c] = b2s[c];
        #pragma unroll 4
        for (int k = 0; k < DH; k++) {
            float a = Ts[tid * 65 + k];
            #pragma unroll
            for (int c = 0; c < NCLS; c++) s[c] = fmaf(a, W2s[k * NCLS + c], s[c]);
        }
        float* o = out + (size_t)(row0 + tid) * NCLS;
        #pragma unroll
        for (int c = 0; c < NCLS; c++) o[c] = s[c];
    }
}

// ---------------------------------------------------------------------------
// launch
// ---------------------------------------------------------------------------
extern "C" void kernel_launch(void* const* d_in, const int* in_sizes, int n_in,
                              void* d_out, int out_size) {
    const float* h   = (const float*)d_in[0];
    const int*   src = (const int*)  d_in[1];
    const int*   dst = (const int*)  d_in[2];
    const float* W0  = (const float*)d_in[3];
    const float* b0  = (const float*)d_in[4];
    const float* W1  = (const float*)d_in[5];
    const float* b1  = (const float*)d_in[6];
    const float* Wl1 = (const float*)d_in[7];
    const float* bl1 = (const float*)d_in[8];
    const float* Wl2 = (const float*)d_in[9];
    const float* bl2 = (const float*)d_in[10];
    float* out = (float*)d_out;

    void *p_agg, *p_hf, *p_w0t, *p_w1t, *p_wl1t;
    cudaGetSymbolAddress(&p_agg,  g_agg);
    cudaGetSymbolAddress(&p_hf,   g_hf16);
    cudaGetSymbolAddress(&p_w0t,  g_w0t);
    cudaGetSymbolAddress(&p_w1t,  g_w1t);
    cudaGetSymbolAddress(&p_wl1t, g_wl1t);
    __half* agg  = (__half*)p_agg;
    __half* hf   = (__half*)p_hf;
    __half* w0t  = (__half*)p_w0t;
    __half* w1t  = (__half*)p_w1t;
    __half* wl1t = (__half*)p_wl1t;

    cudaFuncSetAttribute(mma_gemm_kernel<true>,
                         cudaFuncAttributeMaxDynamicSharedMemorySize, MM_SMEM_BYTES);
    cudaFuncSetAttribute(mma_gemm_kernel<false>,
                         cudaFuncAttributeMaxDynamicSharedMemorySize, MM_SMEM_BYTES);
    cudaFuncSetAttribute(head_kernel,
                         cudaFuncAttributeMaxDynamicSharedMemorySize, HD_SMEM_BYTES);

    const int NB_E = (NEDGES + 255) / 256;
    const int NB_A = (NNODES * 16 + 255) / 256;       // half-warp-per-node grid
    const int NB_M = (NNODES + 127) / 128;            // 313 MMA tiles
    const int NB_H = NNODES / 64;                     // 625 head tiles

    // preprocessing: 3 launches (weight transpose folded into histogram)
    hist_wprep_kernel<<<NB_E, 256>>>(src, dst, W0, W1, Wl1);
    scan_norms_kernel<<<NPART, SCAN_BLK>>>();
    scatter_conv_kernel<<<NB_E, 256>>>(src, dst, h);

    // layer 0 (GEMM writes h1 pre-scaled by norm_out for the next aggregation)
    aggregate_kernel<<<NB_A, 256>>>(hf, agg);
    mma_gemm_kernel<true><<<NB_M, 256, MM_SMEM_BYTES>>>(agg, w0t, b0, hf);
    // layer 1 (plain output; feeds the head)
    aggregate_kernel<<<NB_A, 256>>>(hf, agg);
    mma_gemm_kernel<false><<<NB_M, 256, MM_SMEM_BYTES>>>(agg, w1t, b1, hf);
    // fused HMMA MLP head
    head_kernel<<<NB_H, 128, HD_SMEM_BYTES>>>(hf, wl1t, bl1, Wl2, bl2, out);
}